// round 11
// baseline (speedup 1.0000x reference)
#include <cuda_runtime.h>
#include <math.h>

// ---------------- problem constants ----------------
#define Bsz  16384      // tokens
#define Fv   8          // features
#define Vv   100000     // vocab
#define Ev   128        // embed dim
#define Dv   1024       // model dim
#define NWv  64         // wide features
#define NEv  16         // experts
#define CAPv 4096       // expert capacity
#define H3   (3*Dv)

// ---------------- device scratch (no cudaMalloc allowed) ----------------
__device__ float g_embf[(size_t)Bsz * Dv];        // embedding flat, reused as h1
__device__ float g_ctx [(size_t)Bsz * Dv];        // context [deep|wide]
__device__ float g_bufA[(size_t)NEv * CAPv * Dv]; // expert input x, then expert output y
__device__ float g_bufH[(size_t)NEv * CAPv * Dv]; // expert hidden
__device__ float g_moe [(size_t)Bsz * Dv];
__device__ float g_h0  [(size_t)Bsz * H3];
__device__ float g_probs[(size_t)Bsz * NEv];
__device__ int   g_topi[Bsz * 2];
__device__ float g_topv[Bsz * 2];
__device__ int   g_dest[2 * Bsz];
__device__ int   g_cnt [NEv];
__device__ float g_psum[NEv];

__device__ __forceinline__ float leaky(float x) { return x >= 0.f ? x : 0.2f * x; }

// ---------------- embedding gather ----------------
__global__ __launch_bounds__(256)
void k_embed(const int* __restrict__ deep_in,
             const float* __restrict__ tables,
             float* __restrict__ embf) {
    int gid = blockIdx.x * blockDim.x + threadIdx.x;   // B*F*E/4 threads
    int e4 = gid & 31;
    int f  = (gid >> 5) & 7;
    int b  = gid >> 8;
    int idx = deep_in[b * Fv + f];
    const float4* src = (const float4*)(tables + ((size_t)f * Vv + idx) * Ev);
    ((float4*)(embf + (size_t)b * Dv + f * Ev))[e4] = src[e4];
}

// ---------------- wide head: ctx[:,512:1024] ----------------
__global__ __launch_bounds__(256)
void k_wide(const float* __restrict__ wide_in,
            const float* __restrict__ wW, const float* __restrict__ wb,
            const float* __restrict__ gamma, const float* __restrict__ beta,
            float* __restrict__ ctx) {
    int t = blockIdx.x;
    __shared__ float xs[NWv];
    if (threadIdx.x < NWv) xs[threadIdx.x] = wide_in[(size_t)t * NWv + threadIdx.x];
    __syncthreads();
    const float inv = 0.9999950000375f;  // 1/sqrt(1+1e-5)
    for (int j = threadIdx.x; j < 512; j += 256) {
        float s = wb[j];
        #pragma unroll 8
        for (int k = 0; k < NWv; k++) s += xs[k] * wW[k * 512 + j];
        s = gamma[j] * s * inv + beta[j];
        ctx[(size_t)t * Dv + 512 + j] = leaky(s);
    }
}

// ---------------- generic fp32 SGEMM: C = act(A@B + bias) ----------------
// 128x128 tile, BK=8, 256 threads, 8x8 per thread.
__global__ __launch_bounds__(256)
void k_sgemm(const float* __restrict__ A, const float* __restrict__ B,
             const float* __restrict__ bias, float* __restrict__ C,
             int M, int lda, int ldb, int ldc, int K, int act,
             const int* __restrict__ segRows,
             long aStr, long bStr, long biStr, long cStr) {
    int e = blockIdx.z;
    if (segRows) { M = segRows[e]; if (M > CAPv) M = CAPv; }
    int row0 = blockIdx.y * 128;
    if (row0 >= M) return;
    A += (size_t)e * aStr; B += (size_t)e * bStr;
    bias += (size_t)e * biStr; C += (size_t)e * cStr;
    int col0 = blockIdx.x * 128;

    __shared__ float As[8][132];   // padded: conflict-free transpose store
    __shared__ float Bs[8][128];

    int tid  = threadIdx.x;
    int arow = tid >> 1;
    int acol = (tid & 1) << 2;
    int brow = tid >> 5;
    int bcol = (tid & 31) << 2;
    int ty = tid >> 4;
    int tx = tid & 15;

    float acc[8][8];
    #pragma unroll
    for (int i = 0; i < 8; i++)
        #pragma unroll
        for (int j = 0; j < 8; j++) acc[i][j] = 0.f;

    bool aok = (row0 + arow) < M;
    const float* Ap = A + (size_t)(row0 + arow) * lda + acol;
    const float* Bp = B + (size_t)brow * ldb + col0 + bcol;

    for (int k0 = 0; k0 < K; k0 += 8) {
        float4 av = aok ? *(const float4*)(Ap + k0) : make_float4(0.f, 0.f, 0.f, 0.f);
        float4 bv = *(const float4*)(Bp + (size_t)k0 * ldb);
        As[acol + 0][arow] = av.x; As[acol + 1][arow] = av.y;
        As[acol + 2][arow] = av.z; As[acol + 3][arow] = av.w;
        *(float4*)&Bs[brow][bcol] = bv;
        __syncthreads();
        #pragma unroll
        for (int k = 0; k < 8; k++) {
            float a[8], b[8];
            *(float4*)(a)     = *(const float4*)&As[k][ty * 8];
            *(float4*)(a + 4) = *(const float4*)&As[k][ty * 8 + 4];
            *(float4*)(b)     = *(const float4*)&Bs[k][tx * 8];
            *(float4*)(b + 4) = *(const float4*)&Bs[k][tx * 8 + 4];
            #pragma unroll
            for (int i = 0; i < 8; i++)
                #pragma unroll
                for (int j = 0; j < 8; j++) acc[i][j] += a[i] * b[j];
        }
        __syncthreads();
    }

    float bv8[8];
    #pragma unroll
    for (int j = 0; j < 8; j++) bv8[j] = bias[col0 + tx * 8 + j];
    #pragma unroll
    for (int i = 0; i < 8; i++) {
        int gr = row0 + ty * 8 + i;
        if (gr >= M) continue;
        float* cp = C + (size_t)gr * ldc + col0 + tx * 8;
        #pragma unroll
        for (int j = 0; j < 8; j++) {
            float v = acc[i][j] + bv8[j];
            if (act) v = leaky(v);
            cp[j] = v;
        }
    }
}

// ---------------- router: logits -> softmax -> top-2 ----------------
__global__ __launch_bounds__(128)
void k_router(const float* __restrict__ ctx, const float* __restrict__ rW,
              float* __restrict__ probs, int* __restrict__ topi,
              float* __restrict__ topv) {
    int t = blockIdx.x;
    __shared__ float xs[Dv];
    __shared__ float lg[NEv];
    const float4* xr = (const float4*)(ctx + (size_t)t * Dv);
    for (int i = threadIdx.x; i < Dv / 4; i += 128) ((float4*)xs)[i] = xr[i];
    __syncthreads();
    int warp = threadIdx.x >> 5, lane = threadIdx.x & 31;
    for (int e = warp; e < NEv; e += 4) {
        float p = 0.f;
        for (int i = lane; i < Dv; i += 32) p += xs[i] * rW[i * NEv + e];
        #pragma unroll
        for (int o = 16; o; o >>= 1) p += __shfl_down_sync(0xffffffffu, p, o);
        if (!lane) lg[e] = p;
    }
    __syncthreads();
    if (threadIdx.x == 0) {
        float m = -1e30f;
        #pragma unroll
        for (int e = 0; e < NEv; e++) m = fmaxf(m, lg[e]);
        float pe[NEv]; float s = 0.f;
        #pragma unroll
        for (int e = 0; e < NEv; e++) { pe[e] = expf(lg[e] - m); s += pe[e]; }
        float inv = 1.0f / s;
        float v1 = -1e30f, v2 = -1e30f; int i1 = 0, i2 = 0;
        #pragma unroll
        for (int e = 0; e < NEv; e++) {
            float p = pe[e] * inv;
            probs[(size_t)t * NEv + e] = p;
            if (p > v1)      { v2 = v1; i2 = i1; v1 = p; i1 = e; }
            else if (p > v2) { v2 = p;  i2 = e; }
        }
        topi[2 * t] = i1; topi[2 * t + 1] = i2;
        topv[2 * t] = v1; topv[2 * t + 1] = v2;
    }
}

// deterministic per-expert prob sum (for aux)
__global__ __launch_bounds__(256)
void k_preduce(const float* __restrict__ probs, float* __restrict__ psum) {
    int e = blockIdx.x;
    __shared__ float sm[256];
    float s = 0.f;
    for (int t = threadIdx.x; t < Bsz; t += 256) s += probs[(size_t)t * NEv + e];
    sm[threadIdx.x] = s; __syncthreads();
    for (int o = 128; o > 0; o >>= 1) {
        if (threadIdx.x < o) sm[threadIdx.x] += sm[threadIdx.x + o];
        __syncthreads();
    }
    if (!threadIdx.x) psum[e] = sm[0];
}

// ---------------- exact stable expert ranks (single block, 256 threads) ----------------
// flat order i in [0, 2T): k = i>>14, t = i & (T-1). pos = stable rank within expert.
// Thread tid owns contiguous items [tid*128, (tid+1)*128) -> scan over thread partials
// preserves the reference's stable ordering exactly.
__global__ __launch_bounds__(256)
void k_assign(const int* __restrict__ topi, int* __restrict__ dest,
              int* __restrict__ cnt) {
    __shared__ int s[NEv * 256];      // 16 KB
    int tid = threadIdx.x;
    int loc[NEv];
    #pragma unroll
    for (int e = 0; e < NEv; e++) loc[e] = 0;
    int base = tid * 128;
    for (int j = 0; j < 128; j++) {
        int i = base + j;
        int k = i >> 14;
        int t = i & (Bsz - 1);
        loc[topi[2 * t + k]]++;
    }
    #pragma unroll
    for (int e = 0; e < NEv; e++) s[e * 256 + tid] = loc[e];
    __syncthreads();
    // Hillis-Steele inclusive scan over 256 thread-partials, per expert
    for (int off = 1; off < 256; off <<= 1) {
        int v[NEv];
        #pragma unroll
        for (int e = 0; e < NEv; e++) v[e] = (tid >= off) ? s[e * 256 + tid - off] : 0;
        __syncthreads();
        #pragma unroll
        for (int e = 0; e < NEv; e++) s[e * 256 + tid] += v[e];
        __syncthreads();
    }
    int run[NEv];
    #pragma unroll
    for (int e = 0; e < NEv; e++) run[e] = s[e * 256 + tid] - loc[e];  // exclusive prefix
    if (tid < NEv) cnt[tid] = s[tid * 256 + 255];
    for (int j = 0; j < 128; j++) {
        int i = base + j;
        int k = i >> 14;
        int t = i & (Bsz - 1);
        int e = topi[2 * t + k];
        int pos = run[e]++;
        dest[i] = (pos < CAPv) ? (e * CAPv + pos) : -1;
    }
}

// scatter ctx rows into expert buffer (kept assignments only)
__global__ __launch_bounds__(256)
void k_scatter(const float* __restrict__ ctx, const int* __restrict__ dest,
               float* __restrict__ bufx) {
    int i = blockIdx.x;               // 0..2T-1
    int d = dest[i];
    if (d < 0) return;
    int t = i & (Bsz - 1);
    const float4* src = (const float4*)(ctx + (size_t)t * Dv);
    float4* dst = (float4*)(bufx + (size_t)d * Dv);
    dst[threadIdx.x] = src[threadIdx.x];   // 256 threads * float4 = 1024 floats
}

// combine: moe[t] = w0*y[d0] + w1*y[d1]
__global__ __launch_bounds__(256)
void k_combine(const float* __restrict__ y, const int* __restrict__ dest,
               const float* __restrict__ topv, float* __restrict__ moe) {
    int t = blockIdx.x;
    int d0 = dest[t], d1 = dest[Bsz + t];
    float w0 = topv[2 * t], w1 = topv[2 * t + 1];
    int c = threadIdx.x;
    float rx = 0.f, ry = 0.f, rz = 0.f, rw = 0.f;
    if (d0 >= 0) {
        float4 v = ((const float4*)(y + (size_t)d0 * Dv))[c];
        rx = w0 * v.x; ry = w0 * v.y; rz = w0 * v.z; rw = w0 * v.w;
    }
    if (d1 >= 0) {
        float4 v = ((const float4*)(y + (size_t)d1 * Dv))[c];
        rx += w1 * v.x; ry += w1 * v.y; rz += w1 * v.z; rw += w1 * v.w;
    }
    float4 o = make_float4(rx, ry, rz, rw);
    ((float4*)(moe + (size_t)t * Dv))[c] = o;
}

// final GEMV + sigmoid: out[t] = sigmoid(h1[t]@out_W + out_b)
__global__ __launch_bounds__(256)
void k_out(const float* __restrict__ h1, const float* __restrict__ oW,
           const float* __restrict__ ob, float* __restrict__ out) {
    int t = blockIdx.x * 8 + (threadIdx.x >> 5);
    int lane = threadIdx.x & 31;
    const float* x = h1 + (size_t)t * Dv;
    float s = 0.f;
    for (int i = lane; i < Dv; i += 32) s += x[i] * oW[i];
    #pragma unroll
    for (int o = 16; o; o >>= 1) s += __shfl_down_sync(0xffffffffu, s, o);
    if (!lane) out[t] = 1.0f / (1.0f + expf(-(s + ob[0])));
}

// aux = NE * sum_e (cnt[e]/(2T)) * (psum[e]/T)
__global__ __launch_bounds__(32)
void k_aux(const int* __restrict__ cnt, const float* __restrict__ psum,
           float* __restrict__ aux) {
    if (threadIdx.x) return;
    float s = 0.f;
    #pragma unroll
    for (int e = 0; e < NEv; e++)
        s += ((float)cnt[e] / (2.0f * (float)Bsz)) * (psum[e] / (float)Bsz);
    *aux = (float)NEv * s;
}

// ---------------- launch ----------------
extern "C" void kernel_launch(void* const* d_in, const int* in_sizes, int n_in,
                              void* d_out, int out_size) {
    const int*   deep_in = (const int*)  d_in[0];
    const float* wide_in = (const float*)d_in[1];
    const float* tables  = (const float*)d_in[2];
    const float* deep_W  = (const float*)d_in[3];
    const float* deep_b  = (const float*)d_in[4];
    const float* wide_W  = (const float*)d_in[5];
    const float* wide_b  = (const float*)d_in[6];
    const float* gamma   = (const float*)d_in[7];
    const float* beta    = (const float*)d_in[8];
    const float* rW      = (const float*)d_in[9];
    const float* eW1     = (const float*)d_in[10];
    const float* eb1     = (const float*)d_in[11];
    const float* eW2     = (const float*)d_in[12];
    const float* eb2     = (const float*)d_in[13];
    const float* d0W     = (const float*)d_in[14];
    const float* d0b     = (const float*)d_in[15];
    const float* d1W     = (const float*)d_in[16];
    const float* d1b     = (const float*)d_in[17];
    const float* oW      = (const float*)d_in[18];
    const float* ob      = (const float*)d_in[19];
    float* out = (float*)d_out;

    float *embf, *ctx, *bufA, *bufH, *moe, *h0, *probs, *topv, *psum;
    int *topi, *dest, *cnt;
    cudaGetSymbolAddress((void**)&embf,  g_embf);
    cudaGetSymbolAddress((void**)&ctx,   g_ctx);
    cudaGetSymbolAddress((void**)&bufA,  g_bufA);
    cudaGetSymbolAddress((void**)&bufH,  g_bufH);
    cudaGetSymbolAddress((void**)&moe,   g_moe);
    cudaGetSymbolAddress((void**)&h0,    g_h0);
    cudaGetSymbolAddress((void**)&probs, g_probs);
    cudaGetSymbolAddress((void**)&topi,  g_topi);
    cudaGetSymbolAddress((void**)&topv,  g_topv);
    cudaGetSymbolAddress((void**)&dest,  g_dest);
    cudaGetSymbolAddress((void**)&cnt,   g_cnt);
    cudaGetSymbolAddress((void**)&psum,  g_psum);

    // 1. embedding gather
    k_embed<<<(Bsz * Fv * Ev / 4) / 256, 256>>>(deep_in, tables, embf);
    // 2. wide head -> ctx[:,512:]
    k_wide<<<Bsz, 256>>>(wide_in, wide_W, wide_b, gamma, beta, ctx);
    // 3. deep head GEMM -> ctx[:,:512]   (M=B, N=512, K=1024)
    {
        dim3 g(512 / 128, Bsz / 128, 1);
        k_sgemm<<<g, 256>>>(embf, deep_W, deep_b, ctx,
                            Bsz, Dv, 512, Dv, Dv, 1, nullptr, 0, 0, 0, 0);
    }
    // 4. router + softmax + top-2
    k_router<<<Bsz, 128>>>(ctx, rW, probs, topi, topv);
    // 5. deterministic prob sums (aux)
    k_preduce<<<NEv, 256>>>(probs, psum);
    // 6. exact stable capacity assignment
    k_assign<<<1, 256>>>(topi, dest, cnt);
    // 7. scatter tokens into expert buffer
    k_scatter<<<2 * Bsz, 256>>>(ctx, dest, bufA);
    // 8. expert FFN (segmented GEMMs, row-guarded)
    {
        dim3 g(Dv / 128, CAPv / 128, NEv);
        k_sgemm<<<g, 256>>>(bufA, eW1, eb1, bufH, 0, Dv, Dv, Dv, Dv, 1,
                            cnt, (long)CAPv * Dv, (long)Dv * Dv, Dv, (long)CAPv * Dv);
        k_sgemm<<<g, 256>>>(bufH, eW2, eb2, bufA, 0, Dv, Dv, Dv, Dv, 0,
                            cnt, (long)CAPv * Dv, (long)Dv * Dv, Dv, (long)CAPv * Dv);
    }
    // 9. gather + gate-weighted combine
    k_combine<<<Bsz, 256>>>(bufA, dest, topv, moe);
    // 10. dense head d0: (B,1024)x(1024,3072), leaky
    {
        dim3 g(H3 / 128, Bsz / 128, 1);
        k_sgemm<<<g, 256>>>(moe, d0W, d0b, h0,
                            Bsz, Dv, H3, H3, Dv, 1, nullptr, 0, 0, 0, 0);
    }
    // 11. dense head d1: (B,3072)x(3072,1024), leaky  (h1 reuses embf)
    {
        dim3 g(Dv / 128, Bsz / 128, 1);
        k_sgemm<<<g, 256>>>(h0, d1W, d1b, embf,
                            Bsz, H3, Dv, Dv, H3, 1, nullptr, 0, 0, 0, 0);
    }
    // 12. final GEMV + sigmoid
    k_out<<<Bsz / 8, 256>>>(embf, oW, ob, out);
    // 13. aux scalar
    if (out_size > Bsz) k_aux<<<1, 32>>>(cnt, psum, out + Bsz);
}

// round 14
// speedup vs baseline: 5.3380x; 5.3380x over previous
#include <cuda_runtime.h>
#include <cuda_bf16.h>
#include <stdint.h>
#include <math.h>

typedef __nv_bfloat16  bf16;
typedef __nv_bfloat162 bf162;

// ---------------- problem constants ----------------
#define Bsz  16384      // tokens
#define Fv   8          // features
#define Vv   100000     // vocab
#define Ev   128        // embed dim
#define Dv   1024       // model dim
#define NWv  64         // wide features
#define NEv  16         // experts
#define CAPv 4096       // expert capacity
#define H3   (3*Dv)

// ---------------- device scratch (bf16 activations + transposed bf16 weights) ----
__device__ bf16  gb_emb [(size_t)Bsz * Dv];        // embeddings; later reused as h1
__device__ bf16  gb_ctx [(size_t)Bsz * Dv];        // context [deep|wide]
__device__ bf16  gb_bufA[(size_t)NEv * CAPv * Dv]; // expert input x; later expert out y
__device__ bf16  gb_bufH[(size_t)NEv * CAPv * Dv]; // expert hidden
__device__ bf16  gb_moe [(size_t)Bsz * Dv];
__device__ bf16  gb_h0  [(size_t)Bsz * H3];
__device__ bf16  gw_deep[(size_t)512 * Dv];        // Wt[n][k]
__device__ bf16  gw_e1  [(size_t)NEv * Dv * Dv];
__device__ bf16  gw_e2  [(size_t)NEv * Dv * Dv];
__device__ bf16  gw_d0  [(size_t)H3 * Dv];
__device__ bf16  gw_d1  [(size_t)Dv * H3];
__device__ __align__(16) bf16 gw_r[NEv * Dv];      // router Wt[e][k]
__device__ float g_probs[(size_t)Bsz * NEv];
__device__ int   g_topi[Bsz * 2];
__device__ float g_topv[Bsz * 2];
__device__ int   g_dest[2 * Bsz];
__device__ int   g_cnt [NEv];
__device__ float g_psum[NEv];

__device__ __forceinline__ float leaky(float x) { return x >= 0.f ? x : 0.2f * x; }

// ---------------- weight convert + transpose: Wt[n][k] = bf16(W[k][n]) ----------
__global__ __launch_bounds__(256)
void k_wconv(const float* __restrict__ W, bf16* __restrict__ Wt, int K, int N,
             long wStr, long tStr) {
    int e = blockIdx.z;
    W  += (size_t)e * wStr;
    Wt += (size_t)e * tStr;
    __shared__ float t[32][33];
    int k0 = blockIdx.y * 32, n0 = blockIdx.x * 32;
    int tx = threadIdx.x & 31, ty = threadIdx.x >> 5;   // 32 x 8
    #pragma unroll
    for (int i = 0; i < 32; i += 8)
        t[ty + i][tx] = W[(size_t)(k0 + ty + i) * N + n0 + tx];
    __syncthreads();
    #pragma unroll
    for (int i = 0; i < 32; i += 8)
        Wt[(size_t)(n0 + ty + i) * K + k0 + tx] = __float2bfloat16(t[tx][ty + i]);
}

// router weight: gw_r[e][k] = bf16(rW[k*16+e])
__global__ __launch_bounds__(1024)
void k_rwconv(const float* __restrict__ rW, bf16* __restrict__ rwt) {
    int e = blockIdx.x, k = threadIdx.x;
    rwt[e * Dv + k] = __float2bfloat16(rW[k * NEv + e]);
}

// ---------------- embedding gather -> bf16 ----------------
__global__ __launch_bounds__(256)
void k_embed(const int* __restrict__ deep_in,
             const float* __restrict__ tables,
             bf16* __restrict__ embf) {
    int gid = blockIdx.x * blockDim.x + threadIdx.x;   // B*F*E/4 threads
    int e4 = gid & 31;
    int f  = (gid >> 5) & 7;
    int b  = gid >> 8;
    int idx = deep_in[b * Fv + f];
    float4 v = ((const float4*)(tables + ((size_t)f * Vv + idx) * Ev))[e4];
    bf16* dst = embf + (size_t)b * Dv + f * Ev + e4 * 4;
    *(bf162*)(dst)     = __floats2bfloat162_rn(v.x, v.y);
    *(bf162*)(dst + 2) = __floats2bfloat162_rn(v.z, v.w);
}

// ---------------- wide head: ctx[:,512:1024] (bf16 out) ----------------
__global__ __launch_bounds__(256)
void k_wide(const float* __restrict__ wide_in,
            const float* __restrict__ wW, const float* __restrict__ wb,
            const float* __restrict__ gamma, const float* __restrict__ beta,
            bf16* __restrict__ ctx) {
    int t = blockIdx.x;
    __shared__ float xs[NWv];
    if (threadIdx.x < NWv) xs[threadIdx.x] = wide_in[(size_t)t * NWv + threadIdx.x];
    __syncthreads();
    const float inv = 0.9999950000375f;  // 1/sqrt(1+1e-5)
    for (int j = threadIdx.x; j < 512; j += 256) {
        float s = wb[j];
        #pragma unroll 8
        for (int k = 0; k < NWv; k++) s += xs[k] * wW[k * 512 + j];
        s = gamma[j] * s * inv + beta[j];
        ctx[(size_t)t * Dv + 512 + j] = __float2bfloat16(leaky(s));
    }
}

// ---------------- bf16 tensor-core GEMM: C = act(A@Bt^T + bias), bf16 out -------
// A (M,K) row-major bf16, Bt (N,K) row-major bf16 (pre-transposed weights).
// CTA 128x128x32, 8 warps (4x2), warp tile 32x64, mma m16n8k16, cp.async x2 stages.
#define PADK 40   // smem row stride in bf16 (20 words): conflict-free fragment loads
__global__ __launch_bounds__(256)
void k_hgemm(const bf16* __restrict__ A, const bf16* __restrict__ Bt,
             const float* __restrict__ bias, bf16* __restrict__ C,
             int M, int N, int K, int ldc, int act,
             const int* __restrict__ segRows,
             long aStr, long bStr, long biStr, long cStr) {
    int e = blockIdx.z;
    if (segRows) { M = segRows[e]; if (M > CAPv) M = CAPv; }
    int m0 = blockIdx.y * 128;
    if (m0 >= M) return;
    int n0 = blockIdx.x * 128;
    A    += (size_t)e * aStr;
    Bt   += (size_t)e * bStr;
    bias += (size_t)e * biStr;
    C    += (size_t)e * cStr;

    __shared__ __align__(16) bf16 sA[2][128 * PADK];
    __shared__ __align__(16) bf16 sB[2][128 * PADK];

    int tid  = threadIdx.x;
    int lane = tid & 31;
    int wid  = tid >> 5;
    int wm   = wid & 3;     // warp row (4)
    int wn   = wid >> 2;    // warp col (2)

    float acc[2][8][4];
    #pragma unroll
    for (int i = 0; i < 2; i++)
        #pragma unroll
        for (int j = 0; j < 8; j++)
            #pragma unroll
            for (int q = 0; q < 4; q++) acc[i][j][q] = 0.f;

    int lrow  = tid >> 2;        // 0..63
    int chunk = tid & 3;         // 16B chunk within 64B row

    int KT = K >> 5;             // K / 32

    load0: ;
    // stage 0 prefetch
    {
        int k0 = 0;
        #pragma unroll
        for (int p = 0; p < 2; p++) {
            int r = lrow + p * 64;
            const bf16* ga = A + (size_t)(m0 + r) * K + k0 + chunk * 8;
            unsigned int sa = (unsigned int)__cvta_generic_to_shared(
                &sA[0][r * PADK + chunk * 8]);
            asm volatile("cp.async.cg.shared.global [%0], [%1], 16;"
                         :: "r"(sa), "l"(ga) : "memory");
            const bf16* gb = Bt + (size_t)(n0 + r) * K + k0 + chunk * 8;
            unsigned int sb = (unsigned int)__cvta_generic_to_shared(
                &sB[0][r * PADK + chunk * 8]);
            asm volatile("cp.async.cg.shared.global [%0], [%1], 16;"
                         :: "r"(sb), "l"(gb) : "memory");
        }
        asm volatile("cp.async.commit_group;" ::: "memory");
    }

    for (int kt = 0; kt < KT; kt++) {
        int s = kt & 1;
        if (kt + 1 < KT) {
            int k0 = (kt + 1) << 5;
            int s2 = s ^ 1;
            #pragma unroll
            for (int p = 0; p < 2; p++) {
                int r = lrow + p * 64;
                const bf16* ga = A + (size_t)(m0 + r) * K + k0 + chunk * 8;
                unsigned int sa = (unsigned int)__cvta_generic_to_shared(
                    &sA[s2][r * PADK + chunk * 8]);
                asm volatile("cp.async.cg.shared.global [%0], [%1], 16;"
                             :: "r"(sa), "l"(ga) : "memory");
                const bf16* gb = Bt + (size_t)(n0 + r) * K + k0 + chunk * 8;
                unsigned int sb = (unsigned int)__cvta_generic_to_shared(
                    &sB[s2][r * PADK + chunk * 8]);
                asm volatile("cp.async.cg.shared.global [%0], [%1], 16;"
                             :: "r"(sb), "l"(gb) : "memory");
            }
            asm volatile("cp.async.commit_group;" ::: "memory");
            asm volatile("cp.async.wait_group 1;" ::: "memory");
        } else {
            asm volatile("cp.async.wait_group 0;" ::: "memory");
        }
        __syncthreads();

        const unsigned int* baseA = (const unsigned int*)&sA[s][0];
        const unsigned int* baseB = (const unsigned int*)&sB[s][0];
        #pragma unroll
        for (int ks = 0; ks < 2; ks++) {
            unsigned int af[2][4];
            #pragma unroll
            for (int mm = 0; mm < 2; mm++) {
                int r  = wm * 32 + mm * 16 + (lane >> 2);
                int w0 = r * 20 + ks * 8 + (lane & 3);
                af[mm][0] = baseA[w0];
                af[mm][1] = baseA[w0 + 8 * 20];
                af[mm][2] = baseA[w0 + 4];
                af[mm][3] = baseA[w0 + 8 * 20 + 4];
            }
            #pragma unroll
            for (int nn = 0; nn < 8; nn++) {
                int n  = wn * 64 + nn * 8 + (lane >> 2);
                int w0 = n * 20 + ks * 8 + (lane & 3);
                unsigned int b0 = baseB[w0];
                unsigned int b1 = baseB[w0 + 4];
                #pragma unroll
                for (int mm = 0; mm < 2; mm++) {
                    float* c = acc[mm][nn];
                    asm volatile(
                        "mma.sync.aligned.m16n8k16.row.col.f32.bf16.bf16.f32 "
                        "{%0,%1,%2,%3}, {%4,%5,%6,%7}, {%8,%9}, {%0,%1,%2,%3};"
                        : "+f"(c[0]), "+f"(c[1]), "+f"(c[2]), "+f"(c[3])
                        : "r"(af[mm][0]), "r"(af[mm][1]),
                          "r"(af[mm][2]), "r"(af[mm][3]),
                          "r"(b0), "r"(b1));
                }
            }
        }
        __syncthreads();
    }

    // ---- epilogue: bias + optional leaky, bf16 store ----
    #pragma unroll
    for (int mm = 0; mm < 2; mm++) {
        int rbase = m0 + wm * 32 + mm * 16 + (lane >> 2);
        #pragma unroll
        for (int h = 0; h < 2; h++) {
            int r = rbase + h * 8;
            if (r >= M) continue;
            bf16* crow = C + (size_t)r * ldc + n0;
            #pragma unroll
            for (int nn = 0; nn < 8; nn++) {
                int cidx = wn * 64 + nn * 8 + (lane & 3) * 2;
                float v0 = acc[mm][nn][h * 2 + 0] + bias[n0 + cidx];
                float v1 = acc[mm][nn][h * 2 + 1] + bias[n0 + cidx + 1];
                if (act) { v0 = leaky(v0); v1 = leaky(v1); }
                *(bf162*)&crow[cidx] = __floats2bfloat162_rn(v0, v1);
            }
        }
    }
}

// ---------------- router: bf16 ctx @ smem bf16 rWt -> softmax -> top2 ------------
// 512 blocks x 256 threads; 8 warps/block, 4 tokens/warp; rWt staged in smem once.
__global__ __launch_bounds__(256)
void k_router(const bf16* __restrict__ ctx, const bf16* __restrict__ rwt,
              float* __restrict__ probs, int* __restrict__ topi,
              float* __restrict__ topv) {
    __shared__ __align__(16) bf16 srw[NEv * Dv];   // 32 KB
    int tid = threadIdx.x;
    const uint4* src = (const uint4*)rwt;
    uint4* dst = (uint4*)srw;
    #pragma unroll
    for (int i = 0; i < 8; i++) dst[tid + i * 256] = src[tid + i * 256];
    __syncthreads();

    int wid = tid >> 5, lane = tid & 31;
    const bf162* srw2 = (const bf162*)srw;
    for (int tt = 0; tt < 4; tt++) {
        int t = blockIdx.x * 32 + wid * 4 + tt;
        // token row into registers (32 bf16 per lane = 16 bf162 words)
        const bf162* xr = (const bf162*)(ctx + (size_t)t * Dv);
        float xf[32];
        #pragma unroll
        for (int i = 0; i < 16; i++) {
            float2 p = __bfloat1622float2(xr[lane + i * 32]);
            xf[2 * i] = p.x; xf[2 * i + 1] = p.y;
        }
        float lg[NEv];
        #pragma unroll
        for (int eidx = 0; eidx < NEv; eidx++) {
            float s = 0.f;
            const bf162* wr = srw2 + eidx * (Dv / 2);
            #pragma unroll
            for (int i = 0; i < 16; i++) {
                float2 w = __bfloat1622float2(wr[lane + i * 32]);
                s += xf[2 * i] * w.x + xf[2 * i + 1] * w.y;
            }
            #pragma unroll
            for (int o = 16; o; o >>= 1) s += __shfl_down_sync(0xffffffffu, s, o);
            lg[eidx] = s;   // valid on lane 0
        }
        if (lane == 0) {
            float m = -1e30f;
            #pragma unroll
            for (int eidx = 0; eidx < NEv; eidx++) m = fmaxf(m, lg[eidx]);
            float pe[NEv]; float s = 0.f;
            #pragma unroll
            for (int eidx = 0; eidx < NEv; eidx++) { pe[eidx] = expf(lg[eidx] - m); s += pe[eidx]; }
            float inv = 1.0f / s;
            float v1 = -1e30f, v2 = -1e30f; int i1 = 0, i2 = 0;
            #pragma unroll
            for (int eidx = 0; eidx < NEv; eidx++) {
                float p = pe[eidx] * inv;
                probs[(size_t)t * NEv + eidx] = p;
                if (p > v1)      { v2 = v1; i2 = i1; v1 = p; i1 = eidx; }
                else if (p > v2) { v2 = p;  i2 = eidx; }
            }
            topi[2 * t] = i1; topi[2 * t + 1] = i2;
            topv[2 * t] = v1; topv[2 * t + 1] = v2;
        }
    }
}

// deterministic per-expert prob sum (for aux)
__global__ __launch_bounds__(256)
void k_preduce(const float* __restrict__ probs, float* __restrict__ psum) {
    int e = blockIdx.x;
    __shared__ float sm[256];
    float s = 0.f;
    for (int t = threadIdx.x; t < Bsz; t += 256) s += probs[(size_t)t * NEv + e];
    sm[threadIdx.x] = s; __syncthreads();
    for (int o = 128; o > 0; o >>= 1) {
        if (threadIdx.x < o) sm[threadIdx.x] += sm[threadIdx.x + o];
        __syncthreads();
    }
    if (!threadIdx.x) psum[e] = sm[0];
}

// ---------------- exact stable expert ranks (single block, 256 threads) ---------
__global__ __launch_bounds__(256)
void k_assign(const int* __restrict__ topi, int* __restrict__ dest,
              int* __restrict__ cnt) {
    __shared__ int s[NEv * 256];      // 16 KB
    int tid = threadIdx.x;
    int loc[NEv];
    #pragma unroll
    for (int e = 0; e < NEv; e++) loc[e] = 0;
    int base = tid * 128;
    for (int j = 0; j < 128; j++) {
        int i = base + j;
        int k = i >> 14;
        int t = i & (Bsz - 1);
        loc[topi[2 * t + k]]++;
    }
    #pragma unroll
    for (int e = 0; e < NEv; e++) s[e * 256 + tid] = loc[e];
    __syncthreads();
    for (int off = 1; off < 256; off <<= 1) {
        int v[NEv];
        #pragma unroll
        for (int e = 0; e < NEv; e++) v[e] = (tid >= off) ? s[e * 256 + tid - off] : 0;
        __syncthreads();
        #pragma unroll
        for (int e = 0; e < NEv; e++) s[e * 256 + tid] += v[e];
        __syncthreads();
    }
    int run[NEv];
    #pragma unroll
    for (int e = 0; e < NEv; e++) run[e] = s[e * 256 + tid] - loc[e];
    if (tid < NEv) cnt[tid] = s[tid * 256 + 255];
    for (int j = 0; j < 128; j++) {
        int i = base + j;
        int k = i >> 14;
        int t = i & (Bsz - 1);
        int e = topi[2 * t + k];
        int pos = run[e]++;
        dest[i] = (pos < CAPv) ? (e * CAPv + pos) : -1;
    }
}

// scatter bf16 ctx rows into expert buffer
__global__ __launch_bounds__(256)
void k_scatter(const bf16* __restrict__ ctx, const int* __restrict__ dest,
               bf16* __restrict__ bufx) {
    int i = blockIdx.x;               // 0..2T-1
    int d = dest[i];
    if (d < 0) return;
    int t = i & (Bsz - 1);
    const uint2* src = (const uint2*)(ctx + (size_t)t * Dv);
    uint2* dst = (uint2*)(bufx + (size_t)d * Dv);
    dst[threadIdx.x] = src[threadIdx.x];   // 256 * 8B = 2KB row
}

// combine: moe[t] = w0*y[d0] + w1*y[d1]  (bf16 in/out, fp32 math)
__global__ __launch_bounds__(256)
void k_combine(const bf16* __restrict__ y, const int* __restrict__ dest,
               const float* __restrict__ topv, bf16* __restrict__ moe) {
    int t = blockIdx.x;
    int d0 = dest[t], d1 = dest[Bsz + t];
    float w0 = topv[2 * t], w1 = topv[2 * t + 1];
    int c = threadIdx.x;              // handles elems 4c..4c+3
    float r0 = 0.f, r1 = 0.f, r2 = 0.f, r3 = 0.f;
    if (d0 >= 0) {
        const bf162* p = (const bf162*)(y + (size_t)d0 * Dv) + 2 * c;
        float2 a = __bfloat1622float2(p[0]);
        float2 b = __bfloat1622float2(p[1]);
        r0 = w0 * a.x; r1 = w0 * a.y; r2 = w0 * b.x; r3 = w0 * b.y;
    }
    if (d1 >= 0) {
        const bf162* p = (const bf162*)(y + (size_t)d1 * Dv) + 2 * c;
        float2 a = __bfloat1622float2(p[0]);
        float2 b = __bfloat1622float2(p[1]);
        r0 += w1 * a.x; r1 += w1 * a.y; r2 += w1 * b.x; r3 += w1 * b.y;
    }
    bf162* q = (bf162*)(moe + (size_t)t * Dv) + 2 * c;
    q[0] = __floats2bfloat162_rn(r0, r1);
    q[1] = __floats2bfloat162_rn(r2, r3);
}

// final GEMV + sigmoid
__global__ __launch_bounds__(256)
void k_out(const bf16* __restrict__ h1, const float* __restrict__ oW,
           const float* __restrict__ ob, float* __restrict__ out) {
    int t = blockIdx.x * 8 + (threadIdx.x >> 5);
    int lane = threadIdx.x & 31;
    const bf162* x = (const bf162*)(h1 + (size_t)t * Dv);
    float s = 0.f;
    for (int i = lane; i < Dv / 2; i += 32) {
        float2 p = __bfloat1622float2(x[i]);
        s += p.x * oW[2 * i] + p.y * oW[2 * i + 1];
    }
    #pragma unroll
    for (int o = 16; o; o >>= 1) s += __shfl_down_sync(0xffffffffu, s, o);
    if (!lane) out[t] = 1.0f / (1.0f + expf(-(s + ob[0])));
}

// aux = NE * sum_e (cnt[e]/(2T)) * (psum[e]/T)
__global__ __launch_bounds__(32)
void k_aux(const int* __restrict__ cnt, const float* __restrict__ psum,
           float* __restrict__ aux) {
    if (threadIdx.x) return;
    float s = 0.f;
    #pragma unroll
    for (int e = 0; e < NEv; e++)
        s += ((float)cnt[e] / (2.0f * (float)Bsz)) * (psum[e] / (float)Bsz);
    *aux = (float)NEv * s;
}

// ---------------- launch ----------------
extern "C" void kernel_launch(void* const* d_in, const int* in_sizes, int n_in,
                              void* d_out, int out_size) {
    const int*   deep_in = (const int*)  d_in[0];
    const float* wide_in = (const float*)d_in[1];
    const float* tables  = (const float*)d_in[2];
    const float* deep_W  = (const float*)d_in[3];
    const float* deep_b  = (const float*)d_in[4];
    const float* wide_W  = (const float*)d_in[5];
    const float* wide_b  = (const float*)d_in[6];
    const float* gamma   = (const float*)d_in[7];
    const float* beta    = (const float*)d_in[8];
    const float* rW      = (const float*)d_in[9];
    const float* eW1     = (const float*)d_in[10];
    const float* eb1     = (const float*)d_in[11];
    const float* eW2     = (const float*)d_in[12];
    const float* eb2     = (const float*)d_in[13];
    const float* d0W     = (const float*)d_in[14];
    const float* d0b     = (const float*)d_in[15];
    const float* d1W     = (const float*)d_in[16];
    const float* d1b     = (const float*)d_in[17];
    const float* oW      = (const float*)d_in[18];
    const float* ob      = (const float*)d_in[19];
    float* out = (float*)d_out;

    bf16 *emb, *ctx, *bufA, *bufH, *moe, *h0;
    bf16 *wdeep, *we1, *we2, *wd0, *wd1, *wr;
    float *probs, *topv, *psum;
    int *topi, *dest, *cnt;
    cudaGetSymbolAddress((void**)&emb,   gb_emb);
    cudaGetSymbolAddress((void**)&ctx,   gb_ctx);
    cudaGetSymbolAddress((void**)&bufA,  gb_bufA);
    cudaGetSymbolAddress((void**)&bufH,  gb_bufH);
    cudaGetSymbolAddress((void**)&moe,   gb_moe);
    cudaGetSymbolAddress((void**)&h0,    gb_h0);
    cudaGetSymbolAddress((void**)&wdeep, gw_deep);
    cudaGetSymbolAddress((void**)&we1,   gw_e1);
    cudaGetSymbolAddress((void**)&we2,   gw_e2);
    cudaGetSymbolAddress((void**)&wd0,   gw_d0);
    cudaGetSymbolAddress((void**)&wd1,   gw_d1);
    cudaGetSymbolAddress((void**)&wr,    gw_r);
    cudaGetSymbolAddress((void**)&probs, g_probs);
    cudaGetSymbolAddress((void**)&topi,  g_topi);
    cudaGetSymbolAddress((void**)&topv,  g_topv);
    cudaGetSymbolAddress((void**)&dest,  g_dest);
    cudaGetSymbolAddress((void**)&cnt,   g_cnt);
    cudaGetSymbolAddress((void**)&psum,  g_psum);

    // 0. weight conversion + transpose (bf16)
    k_wconv<<<dim3(512/32, Dv/32, 1),   256>>>(deep_W, wdeep, Dv, 512, 0, 0);
    k_wconv<<<dim3(Dv/32, Dv/32, NEv),  256>>>(eW1, we1, Dv, Dv,
                                               (long)Dv*Dv, (long)Dv*Dv);
    k_wconv<<<dim3(Dv/32, Dv/32, NEv),  256>>>(eW2, we2, Dv, Dv,
                                               (long)Dv*Dv, (long)Dv*Dv);
    k_wconv<<<dim3(H3/32, Dv/32, 1),    256>>>(d0W, wd0, Dv, H3, 0, 0);
    k_wconv<<<dim3(Dv/32, H3/32, 1),    256>>>(d1W, wd1, H3, Dv, 0, 0);
    k_rwconv<<<NEv, Dv>>>(rW, wr);

    // 1. embedding gather (bf16)
    k_embed<<<(Bsz * Fv * Ev / 4) / 256, 256>>>(deep_in, tables, emb);
    // 2. wide head -> ctx[:,512:]
    k_wide<<<Bsz, 256>>>(wide_in, wide_W, wide_b, gamma, beta, ctx);
    // 3. deep head GEMM -> ctx[:,:512]   (M=B, N=512, K=1024)
    k_hgemm<<<dim3(512/128, Bsz/128, 1), 256>>>(emb, wdeep, deep_b, ctx,
        Bsz, 512, Dv, Dv, 1, nullptr, 0, 0, 0, 0);
    // 4. router + softmax + top-2
    k_router<<<Bsz/32, 256>>>(ctx, wr, probs, topi, topv);
    // 5. deterministic prob sums (aux)
    k_preduce<<<NEv, 256>>>(probs, psum);
    // 6. exact stable capacity assignment
    k_assign<<<1, 256>>>(topi, dest, cnt);
    // 7. scatter tokens into expert buffer
    k_scatter<<<2 * Bsz, 256>>>(ctx, dest, bufA);
    // 8. expert FFN (segmented tensor-core GEMMs, row-guarded)
    {
        dim3 g(Dv/128, CAPv/128, NEv);
        k_hgemm<<<g, 256>>>(bufA, we1, eb1, bufH, 0, Dv, Dv, Dv, 1,
                            cnt, (long)CAPv*Dv, (long)Dv*Dv, Dv, (long)CAPv*Dv);
        k_hgemm<<<g, 256>>>(bufH, we2, eb2, bufA, 0, Dv, Dv, Dv, 0,
                            cnt, (long)CAPv*Dv, (long)Dv*Dv, Dv, (long)CAPv*Dv);
    }
    // 9. gather + gate-weighted combine
    k_combine<<<Bsz, 256>>>(bufA, dest, topv, moe);
    // 10. dense head d0: (B,1024)x(1024,3072), leaky
    k_hgemm<<<dim3(H3/128, Bsz/128, 1), 256>>>(moe, wd0, d0b, h0,
        Bsz, H3, Dv, H3, 1, nullptr, 0, 0, 0, 0);
    // 11. dense head d1: (B,3072)x(3072,1024), leaky (h1 reuses emb)
    k_hgemm<<<dim3(Dv/128, Bsz/128, 1), 256>>>(h0, wd1, d1b, emb,
        Bsz, Dv, H3, Dv, 1, nullptr, 0, 0, 0, 0);
    // 12. final GEMV + sigmoid
    k_out<<<Bsz/8, 256>>>(emb, oW, ob, out);
    // 13. aux scalar
    if (out_size > Bsz) k_aux<<<1, 32>>>(cnt, psum, out + Bsz);
}